// round 1
// baseline (speedup 1.0000x reference)
#include <cuda_runtime.h>

#define N0 48000
#define N1MAX 32000
#define EPSV 1e-4f

// ---------------- scratch (device globals; no allocation) ----------------
__device__ float g_f0a[(N0 + 1) * 32];
__device__ float g_f0b[(N0 + 1) * 32];
__device__ float g_f0c[(N0 + 1) * 32];
__device__ float g_cat[(N0 + 1) * 64];
__device__ float g_h64[(N0 + 1) * 64];
__device__ float g_f1a[(N1MAX + 1) * 64];
__device__ float g_f1b[(N1MAX + 1) * 64];
__device__ float g_f1c[(N1MAX + 1) * 64];
__device__ int g_nbr0[(N0 + 1) * 27];
__device__ int g_nbr1[(N1MAX + 1) * 27];
__device__ int g_nbrD[(N1MAX + 1) * 8];
__device__ int g_parent[N0 + 1];
__device__ int g_kid[N0 + 1];

// ---------------- small utility kernels ----------------
__global__ void fill_i32(int* p, int count, int val, const int* vptr) {
    int t = blockIdx.x * blockDim.x + threadIdx.x;
    if (t >= count) return;
    p[t] = vptr ? *vptr : val;
}

// nbr[out*K + k] = in   (each (out,k) has at most one real pair; padded pairs
// write the zero-row index into the discarded row n_out -> harmless)
__global__ void scatter_pairs(const int* __restrict__ pin, const int* __restrict__ pout,
                              int total, int P, int K, int* __restrict__ nbr) {
    int t = blockIdx.x * blockDim.x + threadIdx.x;
    if (t >= total) return;
    int k = t / P;
    nbr[pout[t] * K + k] = pin[t];
}

// every level-0 point has exactly one (parent, kid) in the down pairs
__global__ void scatter_parent(const int* __restrict__ din, const int* __restrict__ dout,
                               int total, int P, int n0,
                               int* __restrict__ parent, int* __restrict__ kid) {
    int t = blockIdx.x * blockDim.x + threadIdx.x;
    if (t >= total) return;
    int k = t / P;
    int i = din[t];
    if (i < n0) { parent[i] = dout[t]; kid[i] = k; }
}

// y = relu((x-m)*g*rsqrt(v+eps)+b); rows >= n are written 0 (zero row for gathers)
template <int C>
__global__ void bnrelu_k(const float* __restrict__ x, const float* __restrict__ bn,
                         float* __restrict__ y, int n_host, const int* __restrict__ n_dev,
                         int total) {
    int t = blockIdx.x * blockDim.x + threadIdx.x;
    if (t >= total) return;
    int n = n_dev ? *n_dev : n_host;
    int r = t / C, c = t % C;
    float v = 0.f;
    if (r < n) {
        float g = bn[c], be = bn[C + c], m = bn[2 * C + c], va = bn[3 * C + c];
        v = fmaxf((x[t] - m) * (g * rsqrtf(va + EPSV)) + be, 0.f);
    }
    y[t] = v;
}

// ---------------- gather implicit-GEMM sparse conv ----------------
// out[r, :] = sum_k x[nbr[r][k], :] @ W[k]  (+ res[r, :])
// Tile: 64 rows x COUT cols; thread computes 4x4 register block.
template <int CIN, int COUT>
__global__ void conv_gather(const float* __restrict__ x, const float* __restrict__ W,
                            const int* __restrict__ nbr, int K,
                            const float* __restrict__ res, float* __restrict__ out,
                            int n_host, const int* __restrict__ n_dev) {
    constexpr int BR = 64;
    constexpr int TCOL = COUT / 4;   // thread cols
    constexpr int NT = 16 * TCOL;    // threads per block (128 or 256)
    __shared__ float Xs[BR * (CIN + 1)];
    __shared__ float Ws[CIN * COUT];
    __shared__ int idxs[BR];

    int n = n_dev ? *n_dev : n_host;
    int row0 = blockIdx.x * BR;
    if (row0 >= n) return;
    int tid = threadIdx.x;
    int tc = tid % TCOL, tr = tid / TCOL;

    float acc[4][4] = {};
    for (int k = 0; k < K; ++k) {
        if (tid < BR) {
            int r = row0 + tid;
            idxs[tid] = (r < n) ? nbr[r * K + k] : n;  // n -> zero row
        }
        __syncthreads();
        for (int e = tid; e < BR * CIN; e += NT) {
            int r = e / CIN, c = e % CIN;
            Xs[r * (CIN + 1) + c] = x[idxs[r] * CIN + c];
        }
        for (int e = tid; e < CIN * COUT; e += NT)
            Ws[e] = W[k * CIN * COUT + e];
        __syncthreads();
#pragma unroll
        for (int ci = 0; ci < CIN; ++ci) {
            float xv[4], wv[4];
#pragma unroll
            for (int i = 0; i < 4; i++) xv[i] = Xs[(tr * 4 + i) * (CIN + 1) + ci];
#pragma unroll
            for (int j = 0; j < 4; j++) wv[j] = Ws[ci * COUT + tc * 4 + j];
#pragma unroll
            for (int i = 0; i < 4; i++)
#pragma unroll
                for (int j = 0; j < 4; j++) acc[i][j] += xv[i] * wv[j];
        }
        __syncthreads();
    }
#pragma unroll
    for (int i = 0; i < 4; i++) {
        int r = row0 + tr * 4 + i;
        if (r < n) {
#pragma unroll
            for (int j = 0; j < 4; j++) {
                int c = tc * 4 + j;
                float v = acc[i][j];
                if (res) v += res[r * COUT + c];
                out[r * COUT + c] = v;
            }
        }
    }
}

// dec[i, c] = x1[parent[i], :] @ up_W[kid[i]][:, c]  -> right half of concat buffer
__global__ void up_gather(const float* __restrict__ x1, const float* __restrict__ upW,
                          const int* __restrict__ parent, const int* __restrict__ kid,
                          float* __restrict__ cat, int n0) {
    int t = blockIdx.x * blockDim.x + threadIdx.x;
    if (t >= n0 * 32) return;
    int i = t / 32, c = t % 32;
    const float* xr = x1 + parent[i] * 64;
    const float* w = upW + kid[i] * 64 * 32 + c;
    float a = 0.f;
#pragma unroll
    for (int ci = 0; ci < 64; ++ci) a += xr[ci] * w[ci * 32];
    cat[i * 64 + 32 + c] = a;
}

__global__ void copy_left(const float* __restrict__ src, float* __restrict__ cat, int n0) {
    int t = blockIdx.x * blockDim.x + threadIdx.x;
    if (t >= n0 * 32) return;
    cat[(t / 32) * 64 + (t % 32)] = src[t];
}

// out[i,c] = h[i,c] + cat[i,:] @ Wsc[:,c]
__global__ void wsc_add(const float* __restrict__ h, const float* __restrict__ cat,
                        const float* __restrict__ Wsc, float* __restrict__ out, int n0) {
    int t = blockIdx.x * blockDim.x + threadIdx.x;
    if (t >= n0 * 32) return;
    int i = t / 32, c = t % 32;
    float a = h[t];
    const float* xr = cat + i * 64;
#pragma unroll
    for (int ci = 0; ci < 64; ++ci) a += xr[ci] * Wsc[ci * 32 + c];
    out[t] = a;
}

// ---------------- host-side orchestration ----------------
static inline int ceil_div(int a, int b) { return (a + b - 1) / b; }

extern "C" void kernel_launch(void* const* d_in, const int* in_sizes, int n_in,
                              void* d_out, int out_size) {
    const float* feats     = (const float*)d_in[0];
    const float* res0_W    = (const float*)d_in[1];
    const float* res0_bn   = (const float*)d_in[2];
    const float* down_bn   = (const float*)d_in[3];
    const float* down_W    = (const float*)d_in[4];
    const float* res1_W    = (const float*)d_in[5];
    const float* res1_bn   = (const float*)d_in[6];
    const float* up_bn     = (const float*)d_in[7];
    const float* up_W      = (const float*)d_in[8];
    const float* tail0_bn1 = (const float*)d_in[9];
    const float* tail0_W1  = (const float*)d_in[10];
    const float* tail0_bn2 = (const float*)d_in[11];
    const float* tail0_W2  = (const float*)d_in[12];
    const float* tail0_Wsc = (const float*)d_in[13];
    const float* tail1_W   = (const float*)d_in[14];
    const float* tail1_bn  = (const float*)d_in[15];
    const int* subm0_in    = (const int*)d_in[16];
    const int* subm0_out   = (const int*)d_in[17];
    const int* subm1_in    = (const int*)d_in[18];
    const int* subm1_out   = (const int*)d_in[19];
    const int* down_in     = (const int*)d_in[20];
    const int* down_out    = (const int*)d_in[21];
    const int* n1p         = (const int*)d_in[22];

    const int n0 = in_sizes[0] / 32;
    const int P0 = in_sizes[16] / 27;
    const int P1 = in_sizes[18] / 27;
    const int PD = in_sizes[20] / 8;

    float *f0a, *f0b, *f0c, *cat, *h64, *f1a, *f1b, *f1c;
    int *nbr0, *nbr1, *nbrD, *parent, *kid;
    cudaGetSymbolAddress((void**)&f0a, g_f0a);
    cudaGetSymbolAddress((void**)&f0b, g_f0b);
    cudaGetSymbolAddress((void**)&f0c, g_f0c);
    cudaGetSymbolAddress((void**)&cat, g_cat);
    cudaGetSymbolAddress((void**)&h64, g_h64);
    cudaGetSymbolAddress((void**)&f1a, g_f1a);
    cudaGetSymbolAddress((void**)&f1b, g_f1b);
    cudaGetSymbolAddress((void**)&f1c, g_f1c);
    cudaGetSymbolAddress((void**)&nbr0, g_nbr0);
    cudaGetSymbolAddress((void**)&nbr1, g_nbr1);
    cudaGetSymbolAddress((void**)&nbrD, g_nbrD);
    cudaGetSymbolAddress((void**)&parent, g_parent);
    cudaGetSymbolAddress((void**)&kid, g_kid);

    const int TB = 256;
    // ---- build rulebooks ----
    fill_i32<<<ceil_div((N0 + 1) * 27, TB), TB>>>(nbr0, (N0 + 1) * 27, n0, nullptr);
    scatter_pairs<<<ceil_div(27 * P0, TB), TB>>>(subm0_in, subm0_out, 27 * P0, P0, 27, nbr0);
    fill_i32<<<ceil_div((N1MAX + 1) * 27, TB), TB>>>(nbr1, (N1MAX + 1) * 27, 0, n1p);
    scatter_pairs<<<ceil_div(27 * P1, TB), TB>>>(subm1_in, subm1_out, 27 * P1, P1, 27, nbr1);
    fill_i32<<<ceil_div((N1MAX + 1) * 8, TB), TB>>>(nbrD, (N1MAX + 1) * 8, n0, nullptr);
    scatter_pairs<<<ceil_div(8 * PD, TB), TB>>>(down_in, down_out, 8 * PD, PD, 8, nbrD);
    fill_i32<<<ceil_div(N0 + 1, TB), TB>>>(parent, N0 + 1, 0, n1p);
    fill_i32<<<ceil_div(N0 + 1, TB), TB>>>(kid, N0 + 1, 0, nullptr);
    scatter_parent<<<ceil_div(8 * PD, TB), TB>>>(down_in, down_out, 8 * PD, PD, n0, parent, kid);

    const int G0   = ceil_div(n0, 64);       // conv grid level0
    const int G1   = ceil_div(N1MAX, 64);    // conv grid level1 (early-exit on *n1p)
    const int E032 = (n0 + 1) * 32, E064 = (n0 + 1) * 64;
    const int E164 = (N1MAX + 1) * 64;

    // ---- res0 blocks (level 0, C=32) ----
    const float* x = feats;
    for (int rep = 0; rep < 2; ++rep) {
        bnrelu_k<32><<<ceil_div(E032, TB), TB>>>(x, res0_bn + (rep * 2 + 0) * 128, f0b, n0, nullptr, E032);
        conv_gather<32, 32><<<G0, 128>>>(f0b, res0_W + (rep * 2 + 0) * 27 * 1024, nbr0, 27, nullptr, f0c, n0, nullptr);
        bnrelu_k<32><<<ceil_div(E032, TB), TB>>>(f0c, res0_bn + (rep * 2 + 1) * 128, f0b, n0, nullptr, E032);
        conv_gather<32, 32><<<G0, 128>>>(f0b, res0_W + (rep * 2 + 1) * 27 * 1024, nbr0, 27, x, f0a, n0, nullptr);
        x = f0a;
    }
    // f0a = identity

    // ---- down conv (C0 -> C1) ----
    bnrelu_k<32><<<ceil_div(E032, TB), TB>>>(f0a, down_bn, f0b, n0, nullptr, E032);
    conv_gather<32, 64><<<G1, 256>>>(f0b, down_W, nbrD, 8, nullptr, f1a, 0, n1p);

    // ---- res1 blocks (level 1, C=64) ----
    for (int rep = 0; rep < 2; ++rep) {
        bnrelu_k<64><<<ceil_div(E164, TB), TB>>>(f1a, res1_bn + (rep * 2 + 0) * 256, f1b, 0, n1p, E164);
        conv_gather<64, 64><<<G1, 256>>>(f1b, res1_W + (rep * 2 + 0) * 27 * 4096, nbr1, 27, nullptr, f1c, 0, n1p);
        bnrelu_k<64><<<ceil_div(E164, TB), TB>>>(f1c, res1_bn + (rep * 2 + 1) * 256, f1b, 0, n1p, E164);
        conv_gather<64, 64><<<G1, 256>>>(f1b, res1_W + (rep * 2 + 1) * 27 * 4096, nbr1, 27, f1a, f1a, 0, n1p);
    }

    // ---- up conv + concat ----
    bnrelu_k<64><<<ceil_div(E164, TB), TB>>>(f1a, up_bn, f1b, 0, n1p, E164);
    up_gather<<<ceil_div(n0 * 32, TB), TB>>>(f1b, up_W, parent, kid, cat, n0);
    copy_left<<<ceil_div(n0 * 32, TB), TB>>>(f0a, cat, n0);

    // ---- tail0 ----
    bnrelu_k<64><<<ceil_div(E064, TB), TB>>>(cat, tail0_bn1, h64, n0, nullptr, E064);
    conv_gather<64, 32><<<G0, 128>>>(h64, tail0_W1, nbr0, 27, nullptr, f0b, n0, nullptr);
    bnrelu_k<32><<<ceil_div(E032, TB), TB>>>(f0b, tail0_bn2, f0c, n0, nullptr, E032);
    conv_gather<32, 32><<<G0, 128>>>(f0c, tail0_W2, nbr0, 27, nullptr, f0b, n0, nullptr);
    wsc_add<<<ceil_div(n0 * 32, TB), TB>>>(f0b, cat, tail0_Wsc, f0c, n0);

    // ---- tail1 res block -> d_out ----
    bnrelu_k<32><<<ceil_div(E032, TB), TB>>>(f0c, tail1_bn + 0, f0b, n0, nullptr, E032);
    conv_gather<32, 32><<<G0, 128>>>(f0b, tail1_W, nbr0, 27, nullptr, f0a, n0, nullptr);
    bnrelu_k<32><<<ceil_div(E032, TB), TB>>>(f0a, tail1_bn + 128, f0b, n0, nullptr, E032);
    conv_gather<32, 32><<<G0, 128>>>(f0b, tail1_W + 27 * 1024, nbr0, 27, f0c, (float*)d_out, n0, nullptr);
}

// round 3
// speedup vs baseline: 1.2266x; 1.2266x over previous
#include <cuda_runtime.h>

#define N0 48000
#define N1MAX 32000
#define EPSV 1e-4f

// ---------------- scratch (device globals; no allocation) ----------------
__device__ float g_f0a[(N0 + 1) * 32];
__device__ float g_f0b[(N0 + 1) * 32];
__device__ float g_f0c[(N0 + 1) * 32];
__device__ float g_cat[(N0 + 1) * 64];
__device__ float g_f1a[(N1MAX + 1) * 64];
__device__ float g_f1b[(N1MAX + 1) * 64];
__device__ float g_f1c[(N1MAX + 1) * 64];
__device__ int g_nbr0[(N0 + 1) * 27];
__device__ int g_nbr1[(N1MAX + 1) * 27];
__device__ int g_nbrD[(N1MAX + 1) * 8];
__device__ int g_parent[N0 + 1];
__device__ int g_kid[N0 + 1];

// ---------------- f32x2 helpers (sm_100+) ----------------
union F2U { float2 f2; unsigned long long u; };

__device__ __forceinline__ unsigned long long dup2(float v) {
    unsigned long long r;
    asm("mov.b64 %0, {%1, %1};" : "=l"(r) : "f"(v));
    return r;
}
__device__ __forceinline__ void ffma2(unsigned long long& acc, unsigned long long a,
                                      unsigned long long b) {
    asm("fma.rn.f32x2 %0, %1, %2, %0;" : "+l"(acc) : "l"(a), "l"(b));
}

// ---------------- small utility kernels ----------------
__global__ void fill_i32(int* p, int count, int val, const int* vptr) {
    int t = blockIdx.x * blockDim.x + threadIdx.x;
    if (t >= count) return;
    p[t] = vptr ? *vptr : val;
}

// nbr[out*K + k] = in  (each (out,k) has at most one real pair; pad pairs land
// in the discarded row n_out -> harmless)
__global__ void scatter_pairs(const int* __restrict__ pin, const int* __restrict__ pout,
                              int total, int P, int K, int* __restrict__ nbr) {
    int t = blockIdx.x * blockDim.x + threadIdx.x;
    if (t >= total) return;
    int k = t / P;
    nbr[pout[t] * K + k] = pin[t];
}

__global__ void scatter_parent(const int* __restrict__ din, const int* __restrict__ dout,
                               int total, int P, int n0,
                               int* __restrict__ parent, int* __restrict__ kid) {
    int t = blockIdx.x * blockDim.x + threadIdx.x;
    if (t >= total) return;
    int k = t / P;
    int i = din[t];
    if (i < n0) { parent[i] = dout[t]; kid[i] = k; }
}

// standalone bnrelu (only used for the up path)
template <int C>
__global__ void bnrelu_k(const float* __restrict__ x, const float* __restrict__ bn,
                         float* __restrict__ y, int n_host, const int* __restrict__ n_dev,
                         int total) {
    int t = blockIdx.x * blockDim.x + threadIdx.x;
    if (t >= total) return;
    int n = n_dev ? *n_dev : n_host;
    int r = t / C, c = t % C;
    float v = 0.f;
    if (r < n) {
        float g = bn[c], be = bn[C + c], m = bn[2 * C + c], va = bn[3 * C + c];
        v = fmaxf((x[t] - m) * (g * rsqrtf(va + EPSV)) + be, 0.f);
    }
    y[t] = v;
}

// ---------------- gather implicit-GEMM sparse conv (fused bnrelu, f32x2) ----
// out[r,:] = sum_k bnrelu(x[nbr[r][k],:]) @ W[k]  (+ res[r,:])
// n_out = rows to produce; n_in = valid input rows (gather idx >= n_in -> 0).
// Tile 64 rows x COUT cols; thread owns 4 rows x 4 cols as 2 f32x2-pairs x 4.
template <int CIN, int COUT>
__global__ void conv_gather(const float* __restrict__ x, const float* __restrict__ bn,
                            const float* __restrict__ W,
                            const int* __restrict__ nbr, int K,
                            const float* __restrict__ res, float* __restrict__ out,
                            int nout_h, const int* __restrict__ nout_d,
                            int nin_h, const int* __restrict__ nin_d) {
    constexpr int BR = 64, P = 66;         // even pitch -> aligned LDS.64
    constexpr int TCOL = COUT / 4;
    constexpr int NT = 16 * TCOL;
    __shared__ float Xs[CIN * P];          // transposed: [ci][row]
    __shared__ float Ws[CIN * COUT];
    __shared__ float sc[CIN], bi[CIN];
    __shared__ int idxs[BR];

    int n = nout_d ? *nout_d : nout_h;
    int nin = nin_d ? *nin_d : nin_h;
    int row0 = blockIdx.x * BR;
    if (row0 >= n) return;
    int tid = threadIdx.x;
    int tc = tid % TCOL, tr = tid / TCOL;

    if (tid < CIN) {
        float g = bn[tid], be = bn[CIN + tid], m = bn[2 * CIN + tid], va = bn[3 * CIN + tid];
        float s = g * rsqrtf(va + EPSV);
        sc[tid] = s;
        bi[tid] = be - m * s;
    }

    unsigned long long acc[2][4];
#pragma unroll
    for (int a = 0; a < 2; a++)
#pragma unroll
        for (int j = 0; j < 4; j++) acc[a][j] = 0ull;

    for (int k = 0; k < K; ++k) {
        __syncthreads();  // Xs/Ws reuse; also covers sc/bi on first iter
        if (tid < BR) {
            int r = row0 + tid;
            idxs[tid] = (r < n) ? nbr[r * K + k] : nin;  // >=nin -> zero contribution
        }
        __syncthreads();
        // gather + bnrelu, store transposed
#pragma unroll
        for (int e = tid; e < BR * (CIN / 4); e += NT) {
            int r = e / (CIN / 4), c4 = e % (CIN / 4);
            int idx = idxs[r];
            float4 v = make_float4(0.f, 0.f, 0.f, 0.f);
            if (idx < nin) {
                v = *reinterpret_cast<const float4*>(x + (size_t)idx * CIN + c4 * 4);
                int c = c4 * 4;
                v.x = fmaxf(v.x * sc[c + 0] + bi[c + 0], 0.f);
                v.y = fmaxf(v.y * sc[c + 1] + bi[c + 1], 0.f);
                v.z = fmaxf(v.z * sc[c + 2] + bi[c + 2], 0.f);
                v.w = fmaxf(v.w * sc[c + 3] + bi[c + 3], 0.f);
            }
            Xs[(c4 * 4 + 0) * P + r] = v.x;
            Xs[(c4 * 4 + 1) * P + r] = v.y;
            Xs[(c4 * 4 + 2) * P + r] = v.z;
            Xs[(c4 * 4 + 3) * P + r] = v.w;
        }
#pragma unroll
        for (int e = tid; e < CIN * COUT / 4; e += NT)
            *reinterpret_cast<float4*>(Ws + e * 4) =
                *reinterpret_cast<const float4*>(W + (size_t)k * CIN * COUT + e * 4);
        __syncthreads();
#pragma unroll
        for (int ci = 0; ci < CIN; ++ci) {
            F2U xp0, xp1;
            xp0.f2 = *reinterpret_cast<const float2*>(&Xs[ci * P + tr * 4]);
            xp1.f2 = *reinterpret_cast<const float2*>(&Xs[ci * P + tr * 4 + 2]);
            float4 w = *reinterpret_cast<const float4*>(&Ws[ci * COUT + tc * 4]);
            unsigned long long w0 = dup2(w.x), w1 = dup2(w.y), w2 = dup2(w.z), w3 = dup2(w.w);
            ffma2(acc[0][0], xp0.u, w0);
            ffma2(acc[1][0], xp1.u, w0);
            ffma2(acc[0][1], xp0.u, w1);
            ffma2(acc[1][1], xp1.u, w1);
            ffma2(acc[0][2], xp0.u, w2);
            ffma2(acc[1][2], xp1.u, w2);
            ffma2(acc[0][3], xp0.u, w3);
            ffma2(acc[1][3], xp1.u, w3);
        }
    }
    // epilogue
#pragma unroll
    for (int a = 0; a < 2; a++) {
#pragma unroll
        for (int u = 0; u < 2; u++) {
            int r = row0 + tr * 4 + a * 2 + u;
            if (r < n) {
#pragma unroll
                for (int j = 0; j < 4; j++) {
                    F2U t;
                    t.u = acc[a][j];
                    float v = u ? t.f2.y : t.f2.x;
                    int c = tc * 4 + j;
                    if (res) v += res[(size_t)r * COUT + c];
                    out[(size_t)r * COUT + c] = v;
                }
            }
        }
    }
}

// dec[i,c] = x1b[parent[i],:] @ up_W[kid[i]][:,c]  (x1b pre-bnrelu'd)
__global__ void up_gather(const float* __restrict__ x1, const float* __restrict__ upW,
                          const int* __restrict__ parent, const int* __restrict__ kid,
                          float* __restrict__ cat, int n0) {
    int t = blockIdx.x * blockDim.x + threadIdx.x;
    if (t >= n0 * 32) return;
    int i = t / 32, c = t % 32;
    const float* xr = x1 + (size_t)parent[i] * 64;
    const float* w = upW + (size_t)kid[i] * 64 * 32 + c;
    float a = 0.f;
#pragma unroll
    for (int ci = 0; ci < 64; ++ci) a += xr[ci] * w[ci * 32];
    cat[(size_t)i * 64 + 32 + c] = a;
}

__global__ void copy_left(const float* __restrict__ src, float* __restrict__ cat, int n0) {
    int t = blockIdx.x * blockDim.x + threadIdx.x;
    if (t >= n0 * 32) return;
    cat[(size_t)(t / 32) * 64 + (t % 32)] = src[t];
}

// out[i,c] = h[i,c] + cat[i,:] @ Wsc[:,c]
__global__ void wsc_add(const float* __restrict__ h, const float* __restrict__ cat,
                        const float* __restrict__ Wsc, float* __restrict__ out, int n0) {
    int t = blockIdx.x * blockDim.x + threadIdx.x;
    if (t >= n0 * 32) return;
    int i = t / 32, c = t % 32;
    float a = h[t];
    const float* xr = cat + (size_t)i * 64;
#pragma unroll
    for (int ci = 0; ci < 64; ++ci) a += xr[ci] * Wsc[ci * 32 + c];
    out[t] = a;
}

// ---------------- host-side orchestration ----------------
static inline int ceil_div(int a, int b) { return (a + b - 1) / b; }

extern "C" void kernel_launch(void* const* d_in, const int* in_sizes, int n_in,
                              void* d_out, int out_size) {
    const float* feats     = (const float*)d_in[0];
    const float* res0_W    = (const float*)d_in[1];
    const float* res0_bn   = (const float*)d_in[2];
    const float* down_bn   = (const float*)d_in[3];
    const float* down_W    = (const float*)d_in[4];
    const float* res1_W    = (const float*)d_in[5];
    const float* res1_bn   = (const float*)d_in[6];
    const float* up_bn     = (const float*)d_in[7];
    const float* up_W      = (const float*)d_in[8];
    const float* tail0_bn1 = (const float*)d_in[9];
    const float* tail0_W1  = (const float*)d_in[10];
    const float* tail0_bn2 = (const float*)d_in[11];
    const float* tail0_W2  = (const float*)d_in[12];
    const float* tail0_Wsc = (const float*)d_in[13];
    const float* tail1_W   = (const float*)d_in[14];
    const float* tail1_bn  = (const float*)d_in[15];
    const int* subm0_in    = (const int*)d_in[16];
    const int* subm0_out   = (const int*)d_in[17];
    const int* subm1_in    = (const int*)d_in[18];
    const int* subm1_out   = (const int*)d_in[19];
    const int* down_in     = (const int*)d_in[20];
    const int* down_out    = (const int*)d_in[21];
    const int* n1p         = (const int*)d_in[22];

    const int n0 = in_sizes[0] / 32;
    const int P0 = in_sizes[16] / 27;
    const int P1 = in_sizes[18] / 27;
    const int PD = in_sizes[20] / 8;

    float *f0a, *f0b, *f0c, *cat, *f1a, *f1b, *f1c;
    int *nbr0, *nbr1, *nbrD, *parent, *kid;
    cudaGetSymbolAddress((void**)&f0a, g_f0a);
    cudaGetSymbolAddress((void**)&f0b, g_f0b);
    cudaGetSymbolAddress((void**)&f0c, g_f0c);
    cudaGetSymbolAddress((void**)&cat, g_cat);
    cudaGetSymbolAddress((void**)&f1a, g_f1a);
    cudaGetSymbolAddress((void**)&f1b, g_f1b);
    cudaGetSymbolAddress((void**)&f1c, g_f1c);
    cudaGetSymbolAddress((void**)&nbr0, g_nbr0);
    cudaGetSymbolAddress((void**)&nbr1, g_nbr1);
    cudaGetSymbolAddress((void**)&nbrD, g_nbrD);
    cudaGetSymbolAddress((void**)&parent, g_parent);
    cudaGetSymbolAddress((void**)&kid, g_kid);

    const int TB = 256;
    // ---- build rulebooks ----
    fill_i32<<<ceil_div((N0 + 1) * 27, TB), TB>>>(nbr0, (N0 + 1) * 27, n0, nullptr);
    scatter_pairs<<<ceil_div(27 * P0, TB), TB>>>(subm0_in, subm0_out, 27 * P0, P0, 27, nbr0);
    fill_i32<<<ceil_div((N1MAX + 1) * 27, TB), TB>>>(nbr1, (N1MAX + 1) * 27, 0, n1p);
    scatter_pairs<<<ceil_div(27 * P1, TB), TB>>>(subm1_in, subm1_out, 27 * P1, P1, 27, nbr1);
    fill_i32<<<ceil_div((N1MAX + 1) * 8, TB), TB>>>(nbrD, (N1MAX + 1) * 8, n0, nullptr);
    scatter_pairs<<<ceil_div(8 * PD, TB), TB>>>(down_in, down_out, 8 * PD, PD, 8, nbrD);
    fill_i32<<<ceil_div(N0 + 1, TB), TB>>>(parent, N0 + 1, 0, n1p);
    fill_i32<<<ceil_div(N0 + 1, TB), TB>>>(kid, N0 + 1, 0, nullptr);
    scatter_parent<<<ceil_div(8 * PD, TB), TB>>>(down_in, down_out, 8 * PD, PD, n0, parent, kid);

    const int G0 = ceil_div(n0, 64);
    const int G1 = ceil_div(N1MAX, 64);
    const int E164 = (N1MAX + 1) * 64;

    // ---- res0 blocks (level 0, C=32), bnrelu fused into gather ----
    const float* x = feats;
    for (int rep = 0; rep < 2; ++rep) {
        conv_gather<32, 32><<<G0, 128>>>(x, res0_bn + (rep * 2 + 0) * 128,
                                         res0_W + (size_t)(rep * 2 + 0) * 27 * 1024,
                                         nbr0, 27, nullptr, f0c, n0, nullptr, n0, nullptr);
        conv_gather<32, 32><<<G0, 128>>>(f0c, res0_bn + (rep * 2 + 1) * 128,
                                         res0_W + (size_t)(rep * 2 + 1) * 27 * 1024,
                                         nbr0, 27, x, f0a, n0, nullptr, n0, nullptr);
        x = f0a;
    }
    // f0a = identity

    // ---- down conv (C0 -> C1): n_out = n1 (device), n_in = n0 ----
    conv_gather<32, 64><<<G1, 256>>>(f0a, down_bn, down_W, nbrD, 8, nullptr, f1a,
                                     0, n1p, n0, nullptr);

    // ---- res1 blocks (level 1, C=64): n_out = n_in = n1 ----
    for (int rep = 0; rep < 2; ++rep) {
        conv_gather<64, 64><<<G1, 256>>>(f1a, res1_bn + (rep * 2 + 0) * 256,
                                         res1_W + (size_t)(rep * 2 + 0) * 27 * 4096,
                                         nbr1, 27, nullptr, f1c, 0, n1p, 0, n1p);
        conv_gather<64, 64><<<G1, 256>>>(f1c, res1_bn + (rep * 2 + 1) * 256,
                                         res1_W + (size_t)(rep * 2 + 1) * 27 * 4096,
                                         nbr1, 27, f1a, f1a, 0, n1p, 0, n1p);
    }

    // ---- up conv + concat ----
    bnrelu_k<64><<<ceil_div(E164, TB), TB>>>(f1a, up_bn, f1b, 0, n1p, E164);
    up_gather<<<ceil_div(n0 * 32, TB), TB>>>(f1b, up_W, parent, kid, cat, n0);
    copy_left<<<ceil_div(n0 * 32, TB), TB>>>(f0a, cat, n0);

    // ---- tail0 ----
    conv_gather<64, 32><<<G0, 128>>>(cat, tail0_bn1, tail0_W1, nbr0, 27, nullptr, f0b,
                                     n0, nullptr, n0, nullptr);
    conv_gather<32, 32><<<G0, 128>>>(f0b, tail0_bn2, tail0_W2, nbr0, 27, nullptr, f0c,
                                     n0, nullptr, n0, nullptr);
    wsc_add<<<ceil_div(n0 * 32, TB), TB>>>(f0c, cat, tail0_Wsc, f0b, n0);

    // ---- tail1 res block -> d_out ----
    conv_gather<32, 32><<<G0, 128>>>(f0b, tail1_bn + 0, tail1_W, nbr0, 27, nullptr, f0a,
                                     n0, nullptr, n0, nullptr);
    conv_gather<32, 32><<<G0, 128>>>(f0a, tail1_bn + 128, tail1_W + 27 * 1024, nbr0, 27,
                                     f0b, (float*)d_out, n0, nullptr, n0, nullptr);
}